// round 4
// baseline (speedup 1.0000x reference)
#include <cuda_runtime.h>
#include <math.h>

// ---------------- problem constants ----------------
#define BB   16
#define S1   61
#define SS   (S1*S1)        // 3721
#define BS   (BB*SS)        // 59536
#define DD   128
#define HH   8
#define DHD  16
#define LL   4
#define FFD  512
#define NWIN 61
#define WIN  61
#define KWIN (3*WIN)        // 183
#define PCH  49
#define EPSL 1e-5f

// ---------------- scratch (device globals, no allocation) ----------------
__device__ float g_h [BS*DD];
__device__ float g_t [BS*DD];
__device__ float g_q [BS*DD];
__device__ float g_k [BS*DD];
__device__ float g_v [BS*DD];
__device__ float g_ao[BS*DD];
__device__ float g_ff[BS*FFD];

// ---------------- embed: conv7x7 + relu + linear + pos ----------------
__global__ void embed_kernel(const float* __restrict__ x, const float* __restrict__ cw,
                             const float* __restrict__ cb, const float* __restrict__ ltw,
                             const float* __restrict__ ltb, const float* __restrict__ pos,
                             float* __restrict__ hout) {
    __shared__ float patch[PCH];
    int bid = blockIdx.x;
    int b = bid / SS, s = bid % SS;
    int i = s / S1, j = s % S1;
    int t = threadIdx.x;
    if (t < PCH) {
        float acc = 0.f;
        const float* w = cw + t * 49;
        #pragma unroll
        for (int u = 0; u < 7; u++) {
            int ii = i + u - 3;
            if (ii < 0 || ii >= S1) continue;
            #pragma unroll
            for (int v = 0; v < 7; v++) {
                int jj = j + v - 3;
                if (jj < 0 || jj >= S1) continue;
                acc += x[(b*S1 + ii)*S1 + jj] * w[u*7 + v];
            }
        }
        acc += cb[t];
        patch[t] = fmaxf(acc, 0.f);
    }
    __syncthreads();
    float acc = ltb[t] + pos[(size_t)s*DD + t];
    #pragma unroll
    for (int c = 0; c < PCH; c++)
        acc += patch[c] * ltw[c*DD + t];
    hout[(size_t)bid*DD + t] = acc;
}

// ---------------- layernorm: warp per row (D=128 = 32 lanes x float4) ----------------
__global__ void ln_kernel(const float* __restrict__ x, const float* __restrict__ gs,
                          const float* __restrict__ gb, float* __restrict__ y) {
    int warp = threadIdx.x >> 5, lane = threadIdx.x & 31;
    long long row = (long long)blockIdx.x * 8 + warp;
    if (row >= BS) return;
    float4 v = ((const float4*)(x + row*DD))[lane];
    float sum = v.x + v.y + v.z + v.w;
    float sq  = v.x*v.x + v.y*v.y + v.z*v.z + v.w*v.w;
    #pragma unroll
    for (int o = 16; o; o >>= 1) {
        sum += __shfl_xor_sync(0xffffffffu, sum, o);
        sq  += __shfl_xor_sync(0xffffffffu, sq,  o);
    }
    float mean = sum * (1.f/DD);
    float var  = sq  * (1.f/DD) - mean*mean;
    float rstd = rsqrtf(var + EPSL);
    float4 s4 = ((const float4*)gs)[lane];
    float4 b4 = ((const float4*)gb)[lane];
    float4 o4;
    o4.x = (v.x - mean)*rstd*s4.x + b4.x;
    o4.y = (v.y - mean)*rstd*s4.y + b4.y;
    o4.z = (v.z - mean)*rstd*s4.z + b4.z;
    o4.w = (v.w - mean)*rstd*s4.w + b4.w;
    ((float4*)(y + row*DD))[lane] = o4;
}

// ---------------- generic fp32 GEMM: C = act(alpha*A@W + bias) (+R) ----------------
// BM=64 BN=64 BK=32, 256 threads, 4x4 microtile. N,K multiples of 64/32.
#define GBM 64
#define GBN 64
#define GBK 32

__global__ void __launch_bounds__(256)
gemm_kernel(const float* __restrict__ A, const float* __restrict__ W,
            const float* __restrict__ bias, const float* __restrict__ R,
            float* __restrict__ C, int M, int N, int K, float alpha, int act) {
    __shared__ float As[GBM * (GBK + 1)];   // [m][k], pad 1 -> conflict-free
    __shared__ float Ws[GBK * GBN];         // [k][n]

    int tid = threadIdx.x;
    int tx = tid & 15;        // 16 col-groups
    int ty = tid >> 4;        // 16 row-groups
    int n0 = blockIdx.x * GBN;
    int m0 = blockIdx.y * GBM;

    float acc[4][4];
    #pragma unroll
    for (int i = 0; i < 4; i++)
        #pragma unroll
        for (int j = 0; j < 4; j++) acc[i][j] = 0.f;

    for (int kt = 0; kt < K; kt += GBK) {
        // load A tile 64x32 (coalesced, zero-pad OOB rows)
        #pragma unroll
        for (int r = 0; r < 8; r++) {
            int idx = tid + r * 256;
            int m = idx >> 5, kk = idx & 31;
            int row = m0 + m;
            float val = 0.f;
            if (row < M) val = A[(size_t)row * K + kt + kk];
            As[m * (GBK + 1) + kk] = val;
        }
        // load W tile 32x64 as float4
        #pragma unroll
        for (int r = 0; r < 2; r++) {
            int f = tid + r * 256;
            int kk = f >> 4, c4 = f & 15;
            float4 w4 = *(const float4*)&W[(size_t)(kt + kk) * N + n0 + c4*4];
            *(float4*)&Ws[kk * GBN + c4*4] = w4;
        }
        __syncthreads();

        #pragma unroll
        for (int kk = 0; kk < GBK; kk++) {
            float4 w4 = *(const float4*)&Ws[kk * GBN + tx*4];
            float a0 = As[(ty*4 + 0) * (GBK+1) + kk];
            float a1 = As[(ty*4 + 1) * (GBK+1) + kk];
            float a2 = As[(ty*4 + 2) * (GBK+1) + kk];
            float a3 = As[(ty*4 + 3) * (GBK+1) + kk];
            acc[0][0] += a0*w4.x; acc[0][1] += a0*w4.y; acc[0][2] += a0*w4.z; acc[0][3] += a0*w4.w;
            acc[1][0] += a1*w4.x; acc[1][1] += a1*w4.y; acc[1][2] += a1*w4.z; acc[1][3] += a1*w4.w;
            acc[2][0] += a2*w4.x; acc[2][1] += a2*w4.y; acc[2][2] += a2*w4.z; acc[2][3] += a2*w4.w;
            acc[3][0] += a3*w4.x; acc[3][1] += a3*w4.y; acc[3][2] += a3*w4.z; acc[3][3] += a3*w4.w;
        }
        __syncthreads();
    }

    #pragma unroll
    for (int i = 0; i < 4; i++) {
        int row = m0 + ty*4 + i;
        if (row >= M) continue;
        #pragma unroll
        for (int j = 0; j < 4; j++) {
            int col = n0 + tx*4 + j;
            float vv = acc[i][j] * alpha;
            if (bias) vv += bias[col];
            if (act == 1) vv = fmaxf(vv, 0.f);
            else if (act == 2) vv = 0.5f * vv * (1.f + erff(vv * 0.70710678118654752f));
            if (R) vv += R[(size_t)row * N + col];
            C[(size_t)row * N + col] = vv;
        }
    }
}

// ---------------- windowed local attention ----------------
// grid (NWIN, H, B), 256 threads, dynamic smem.
#define ATTN_SMEM ((WIN*DHD + 2*KWIN*DHD + WIN*(KWIN+1)) * 4)

__global__ void __launch_bounds__(256)
attn_kernel(const float* __restrict__ q, const float* __restrict__ k,
            const float* __restrict__ v, float* __restrict__ ao) {
    extern __shared__ float sm[];
    float* qs = sm;                       // [61][16]
    float* ks = qs + WIN*DHD;             // [183][16]
    float* vs = ks + KWIN*DHD;            // [183][16]
    float* sc = vs + KWIN*DHD;            // [61][184]

    int nw = blockIdx.x, h = blockIdx.y, b = blockIdx.z;
    int t = threadIdx.x;

    // load q window
    for (int idx = t; idx < WIN*DHD; idx += 256) {
        int qi = idx / DHD, d = idx % DHD;
        int s = nw*WIN + qi;
        qs[idx] = q[((size_t)b*SS + s)*DD + h*DHD + d];
    }
    // load k/v for windows nw-1, nw, nw+1 (zero-padded at edges)
    for (int idx = t; idx < KWIN*DHD; idx += 256) {
        int j = idx / DHD, d = idx % DHD;
        int w = nw - 1 + j / WIN;
        int within = j % WIN;
        float kv = 0.f, vv = 0.f;
        if (w >= 0 && w < NWIN) {
            size_t off = ((size_t)b*SS + w*WIN + within)*DD + h*DHD + d;
            kv = k[off]; vv = v[off];
        }
        ks[idx] = kv; vs[idx] = vv;
    }
    __syncthreads();

    int jlo = (nw == 0)      ? WIN   : 0;
    int jhi = (nw == NWIN-1) ? 2*WIN : KWIN;

    // scores [61][183] (masked like reference: -1e9)
    for (int p = t; p < WIN*KWIN; p += 256) {
        int qi = p / KWIN, j = p % KWIN;
        float acc = -1e9f;
        if (j >= jlo && j < jhi) {
            const float4* q4 = (const float4*)(qs + qi*DHD);
            const float4* k4 = (const float4*)(ks + j*DHD);
            acc = 0.f;
            #pragma unroll
            for (int d4 = 0; d4 < 4; d4++) {
                float4 a = q4[d4], c = k4[d4];
                acc += a.x*c.x + a.y*c.y + a.z*c.z + a.w*c.w;
            }
        }
        sc[qi*(KWIN+1) + j] = acc;
    }
    __syncthreads();

    // softmax: warp per row
    int lane = t & 31, warp = t >> 5;
    for (int r = warp; r < WIN; r += 8) {
        float* row = sc + r*(KWIN+1);
        float m = -1e30f;
        for (int j = lane; j < KWIN; j += 32) m = fmaxf(m, row[j]);
        #pragma unroll
        for (int o = 16; o; o >>= 1) m = fmaxf(m, __shfl_xor_sync(0xffffffffu, m, o));
        float sum = 0.f;
        for (int j = lane; j < KWIN; j += 32) {
            float e = __expf(row[j] - m);
            row[j] = e; sum += e;
        }
        #pragma unroll
        for (int o = 16; o; o >>= 1) sum += __shfl_xor_sync(0xffffffffu, sum, o);
        float inv = 1.f / sum;
        for (int j = lane; j < KWIN; j += 32) row[j] *= inv;
    }
    __syncthreads();

    // output: one thread per (qi, d-group-of-4): 61*4 = 244 items
    if (t < WIN*4) {
        int qi = t >> 2, d4 = t & 3;
        const float* row = sc + qi*(KWIN+1);
        float4 acc = make_float4(0.f, 0.f, 0.f, 0.f);
        for (int j = 0; j < KWIN; j++) {
            float p = row[j];
            float4 vv = *(const float4*)(vs + j*DHD + d4*4);
            acc.x += p*vv.x; acc.y += p*vv.y; acc.z += p*vv.z; acc.w += p*vv.w;
        }
        int s = nw*WIN + qi;
        *(float4*)(ao + ((size_t)b*SS + s)*DD + h*DHD + d4*4) = acc;
    }
}

// ---------------- final head: out = A @ pre_w2 + b ----------------
__global__ void head2_kernel(const float* __restrict__ A, const float* __restrict__ w2,
                             const float* __restrict__ b2, float* __restrict__ out) {
    int warp = threadIdx.x >> 5, lane = threadIdx.x & 31;
    long long row = (long long)blockIdx.x * 8 + warp;
    if (row >= BS) return;
    float4 a = ((const float4*)(A + row*DD))[lane];
    float4 w = ((const float4*)w2)[lane];
    float s = a.x*w.x + a.y*w.y + a.z*w.z + a.w*w.w;
    #pragma unroll
    for (int o = 16; o; o >>= 1) s += __shfl_xor_sync(0xffffffffu, s, o);
    if (lane == 0) out[row] = s + b2[0];
}

// ---------------- launch ----------------
extern "C" void kernel_launch(void* const* d_in, const int* in_sizes, int n_in,
                              void* d_out, int out_size) {
    const float* x      = (const float*)d_in[0];
    const float* conv_w = (const float*)d_in[1];
    const float* conv_b = (const float*)d_in[2];
    const float* lt_w   = (const float*)d_in[3];
    const float* lt_b   = (const float*)d_in[4];
    const float* pos    = (const float*)d_in[5];
    const float* ln1_s  = (const float*)d_in[6];
    const float* ln1_b  = (const float*)d_in[7];
    const float* wq     = (const float*)d_in[8];
    const float* wk     = (const float*)d_in[9];
    const float* wv     = (const float*)d_in[10];
    const float* wo     = (const float*)d_in[11];
    const float* wo_b   = (const float*)d_in[12];
    const float* ln2_s  = (const float*)d_in[13];
    const float* ln2_b  = (const float*)d_in[14];
    const float* ff_w1  = (const float*)d_in[15];
    const float* ff_b1  = (const float*)d_in[16];
    const float* ff_w2  = (const float*)d_in[17];
    const float* ff_b2  = (const float*)d_in[18];
    const float* pre_w1 = (const float*)d_in[19];
    const float* pre_b1 = (const float*)d_in[20];
    const float* pre_w2 = (const float*)d_in[21];
    const float* pre_b2 = (const float*)d_in[22];
    float* out = (float*)d_out;

    float *h, *t, *q, *k, *v, *ao, *ff;
    cudaGetSymbolAddress((void**)&h,  g_h);
    cudaGetSymbolAddress((void**)&t,  g_t);
    cudaGetSymbolAddress((void**)&q,  g_q);
    cudaGetSymbolAddress((void**)&k,  g_k);
    cudaGetSymbolAddress((void**)&v,  g_v);
    cudaGetSymbolAddress((void**)&ao, g_ao);
    cudaGetSymbolAddress((void**)&ff, g_ff);

    cudaFuncSetAttribute(attn_kernel, cudaFuncAttributeMaxDynamicSharedMemorySize, ATTN_SMEM);

    embed_kernel<<<BS, 128>>>(x, conv_w, conv_b, lt_w, lt_b, pos, h);

    dim3 gD(DD  / GBN, (BS + GBM - 1) / GBM);   // (2, 931)
    dim3 gF(FFD / GBN, (BS + GBM - 1) / GBM);   // (8, 931)
    int lnGrid = (BS + 7) / 8;

    for (int l = 0; l < LL; l++) {
        ln_kernel<<<lnGrid, 256>>>(h, ln1_s + l*DD, ln1_b + l*DD, t);
        gemm_kernel<<<gD, 256>>>(t, wq + (size_t)l*DD*DD, nullptr, nullptr, q, BS, DD, DD, 0.25f, 0);
        gemm_kernel<<<gD, 256>>>(t, wk + (size_t)l*DD*DD, nullptr, nullptr, k, BS, DD, DD, 1.f,   0);
        gemm_kernel<<<gD, 256>>>(t, wv + (size_t)l*DD*DD, nullptr, nullptr, v, BS, DD, DD, 1.f,   0);
        attn_kernel<<<dim3(NWIN, HH, BB), 256, ATTN_SMEM>>>(q, k, v, ao);
        gemm_kernel<<<gD, 256>>>(ao, wo + (size_t)l*DD*DD, wo_b + l*DD, h, h, BS, DD, DD, 1.f, 0);
        ln_kernel<<<lnGrid, 256>>>(h, ln2_s + l*DD, ln2_b + l*DD, t);
        gemm_kernel<<<gF, 256>>>(t, ff_w1 + (size_t)l*DD*FFD, ff_b1 + l*FFD, nullptr, ff, BS, FFD, DD, 1.f, 2);
        gemm_kernel<<<gD, 256>>>(ff, ff_w2 + (size_t)l*FFD*DD, ff_b2 + l*DD, h, h, BS, DD, FFD, 1.f, 0);
    }

    gemm_kernel<<<gD, 256>>>(h, pre_w1, pre_b1, nullptr, t, BS, DD, DD, 1.f, 1);
    head2_kernel<<<lnGrid, 256>>>(t, pre_w2, pre_b2, out);
}

// round 9
// speedup vs baseline: 1.0005x; 1.0005x over previous
#include <cuda_runtime.h>
#include <math.h>

// ---------------- problem constants ----------------
#define BB   16
#define S1   61
#define SS   (S1*S1)        // 3721
#define BS   (BB*SS)        // 59536
#define DD   128
#define HH   8
#define DHD  16
#define LL   4
#define FFD  512
#define NWIN 61
#define WIN  61
#define KWIN (3*WIN)        // 183
#define PCH  49
#define EPSL 1e-5f

// ---------------- scratch (device globals, no allocation) ----------------
__device__ float g_h [BS*DD];
__device__ float g_t [BS*DD];
__device__ float g_q [BS*DD];
__device__ float g_k [BS*DD];
__device__ float g_v [BS*DD];
__device__ float g_ao[BS*DD];
__device__ float g_ff[BS*FFD];

// ---------------- embed: conv7x7 + relu + linear + pos ----------------
__global__ void embed_kernel(const float* __restrict__ x, const float* __restrict__ cw,
                             const float* __restrict__ cb, const float* __restrict__ ltw,
                             const float* __restrict__ ltb, const float* __restrict__ pos,
                             float* __restrict__ hout) {
    __shared__ float patch[PCH];
    int bid = blockIdx.x;
    int b = bid / SS, s = bid % SS;
    int i = s / S1, j = s % S1;
    int t = threadIdx.x;
    if (t < PCH) {
        float acc = 0.f;
        const float* w = cw + t * 49;
        #pragma unroll
        for (int u = 0; u < 7; u++) {
            int ii = i + u - 3;
            if (ii < 0 || ii >= S1) continue;
            #pragma unroll
            for (int v = 0; v < 7; v++) {
                int jj = j + v - 3;
                if (jj < 0 || jj >= S1) continue;
                acc += x[(b*S1 + ii)*S1 + jj] * w[u*7 + v];
            }
        }
        acc += cb[t];
        patch[t] = fmaxf(acc, 0.f);
    }
    __syncthreads();
    float acc = ltb[t] + pos[(size_t)s*DD + t];
    #pragma unroll
    for (int c = 0; c < PCH; c++)
        acc += patch[c] * ltw[c*DD + t];
    hout[(size_t)bid*DD + t] = acc;
}

// ---------------- layernorm: warp per row (D=128 = 32 lanes x float4) ----------------
__global__ void ln_kernel(const float* __restrict__ x, const float* __restrict__ gs,
                          const float* __restrict__ gb, float* __restrict__ y) {
    int warp = threadIdx.x >> 5, lane = threadIdx.x & 31;
    long long row = (long long)blockIdx.x * 8 + warp;
    if (row >= BS) return;
    float4 v = ((const float4*)(x + row*DD))[lane];
    float sum = v.x + v.y + v.z + v.w;
    float sq  = v.x*v.x + v.y*v.y + v.z*v.z + v.w*v.w;
    #pragma unroll
    for (int o = 16; o; o >>= 1) {
        sum += __shfl_xor_sync(0xffffffffu, sum, o);
        sq  += __shfl_xor_sync(0xffffffffu, sq,  o);
    }
    float mean = sum * (1.f/DD);
    float var  = sq  * (1.f/DD) - mean*mean;
    float rstd = rsqrtf(var + EPSL);
    float4 s4 = ((const float4*)gs)[lane];
    float4 b4 = ((const float4*)gb)[lane];
    float4 o4;
    o4.x = (v.x - mean)*rstd*s4.x + b4.x;
    o4.y = (v.y - mean)*rstd*s4.y + b4.y;
    o4.z = (v.z - mean)*rstd*s4.z + b4.z;
    o4.w = (v.w - mean)*rstd*s4.w + b4.w;
    ((float4*)(y + row*DD))[lane] = o4;
}

// ---------------- generic fp32 GEMM: C = act(alpha*A@W + bias) (+R) ----------------
// BM=64 BN=64 BK=32, 256 threads, 4x4 microtile. N,K multiples of 64/32.
#define GBM 64
#define GBN 64
#define GBK 32

__global__ void __launch_bounds__(256)
gemm_kernel(const float* __restrict__ A, const float* __restrict__ W,
            const float* __restrict__ bias, const float* __restrict__ R,
            float* __restrict__ C, int M, int N, int K, float alpha, int act) {
    __shared__ float As[GBM * (GBK + 1)];   // [m][k], pad 1 -> conflict-free
    __shared__ float Ws[GBK * GBN];         // [k][n]

    int tid = threadIdx.x;
    int tx = tid & 15;        // 16 col-groups
    int ty = tid >> 4;        // 16 row-groups
    int n0 = blockIdx.x * GBN;
    int m0 = blockIdx.y * GBM;

    float acc[4][4];
    #pragma unroll
    for (int i = 0; i < 4; i++)
        #pragma unroll
        for (int j = 0; j < 4; j++) acc[i][j] = 0.f;

    for (int kt = 0; kt < K; kt += GBK) {
        // load A tile 64x32 (coalesced, zero-pad OOB rows)
        #pragma unroll
        for (int r = 0; r < 8; r++) {
            int idx = tid + r * 256;
            int m = idx >> 5, kk = idx & 31;
            int row = m0 + m;
            float val = 0.f;
            if (row < M) val = A[(size_t)row * K + kt + kk];
            As[m * (GBK + 1) + kk] = val;
        }
        // load W tile 32x64 as float4
        #pragma unroll
        for (int r = 0; r < 2; r++) {
            int f = tid + r * 256;
            int kk = f >> 4, c4 = f & 15;
            float4 w4 = *(const float4*)&W[(size_t)(kt + kk) * N + n0 + c4*4];
            *(float4*)&Ws[kk * GBN + c4*4] = w4;
        }
        __syncthreads();

        #pragma unroll
        for (int kk = 0; kk < GBK; kk++) {
            float4 w4 = *(const float4*)&Ws[kk * GBN + tx*4];
            float a0 = As[(ty*4 + 0) * (GBK+1) + kk];
            float a1 = As[(ty*4 + 1) * (GBK+1) + kk];
            float a2 = As[(ty*4 + 2) * (GBK+1) + kk];
            float a3 = As[(ty*4 + 3) * (GBK+1) + kk];
            acc[0][0] += a0*w4.x; acc[0][1] += a0*w4.y; acc[0][2] += a0*w4.z; acc[0][3] += a0*w4.w;
            acc[1][0] += a1*w4.x; acc[1][1] += a1*w4.y; acc[1][2] += a1*w4.z; acc[1][3] += a1*w4.w;
            acc[2][0] += a2*w4.x; acc[2][1] += a2*w4.y; acc[2][2] += a2*w4.z; acc[2][3] += a2*w4.w;
            acc[3][0] += a3*w4.x; acc[3][1] += a3*w4.y; acc[3][2] += a3*w4.z; acc[3][3] += a3*w4.w;
        }
        __syncthreads();
    }

    #pragma unroll
    for (int i = 0; i < 4; i++) {
        int row = m0 + ty*4 + i;
        if (row >= M) continue;
        #pragma unroll
        for (int j = 0; j < 4; j++) {
            int col = n0 + tx*4 + j;
            float vv = acc[i][j] * alpha;
            if (bias) vv += bias[col];
            if (act == 1) vv = fmaxf(vv, 0.f);
            else if (act == 2) vv = 0.5f * vv * (1.f + erff(vv * 0.70710678118654752f));
            if (R) vv += R[(size_t)row * N + col];
            C[(size_t)row * N + col] = vv;
        }
    }
}

// ---------------- windowed local attention ----------------
// grid (NWIN, H, B), 256 threads, dynamic smem.
#define ATTN_SMEM ((WIN*DHD + 2*KWIN*DHD + WIN*(KWIN+1)) * 4)

__global__ void __launch_bounds__(256)
attn_kernel(const float* __restrict__ q, const float* __restrict__ k,
            const float* __restrict__ v, float* __restrict__ ao) {
    extern __shared__ float sm[];
    float* qs = sm;                       // [61][16]
    float* ks = qs + WIN*DHD;             // [183][16]
    float* vs = ks + KWIN*DHD;            // [183][16]
    float* sc = vs + KWIN*DHD;            // [61][184]

    int nw = blockIdx.x, h = blockIdx.y, b = blockIdx.z;
    int t = threadIdx.x;

    // load q window
    for (int idx = t; idx < WIN*DHD; idx += 256) {
        int qi = idx / DHD, d = idx % DHD;
        int s = nw*WIN + qi;
        qs[idx] = q[((size_t)b*SS + s)*DD + h*DHD + d];
    }
    // load k/v for windows nw-1, nw, nw+1 (zero-padded at edges)
    for (int idx = t; idx < KWIN*DHD; idx += 256) {
        int j = idx / DHD, d = idx % DHD;
        int w = nw - 1 + j / WIN;
        int within = j % WIN;
        float kv = 0.f, vv = 0.f;
        if (w >= 0 && w < NWIN) {
            size_t off = ((size_t)b*SS + w*WIN + within)*DD + h*DHD + d;
            kv = k[off]; vv = v[off];
        }
        ks[idx] = kv; vs[idx] = vv;
    }
    __syncthreads();

    int jlo = (nw == 0)      ? WIN   : 0;
    int jhi = (nw == NWIN-1) ? 2*WIN : KWIN;

    // scores [61][183] (masked like reference: -1e9)
    for (int p = t; p < WIN*KWIN; p += 256) {
        int qi = p / KWIN, j = p % KWIN;
        float acc = -1e9f;
        if (j >= jlo && j < jhi) {
            const float4* q4 = (const float4*)(qs + qi*DHD);
            const float4* k4 = (const float4*)(ks + j*DHD);
            acc = 0.f;
            #pragma unroll
            for (int d4 = 0; d4 < 4; d4++) {
                float4 a = q4[d4], c = k4[d4];
                acc += a.x*c.x + a.y*c.y + a.z*c.z + a.w*c.w;
            }
        }
        sc[qi*(KWIN+1) + j] = acc;
    }
    __syncthreads();

    // softmax: warp per row
    int lane = t & 31, warp = t >> 5;
    for (int r = warp; r < WIN; r += 8) {
        float* row = sc + r*(KWIN+1);
        float m = -1e30f;
        for (int j = lane; j < KWIN; j += 32) m = fmaxf(m, row[j]);
        #pragma unroll
        for (int o = 16; o; o >>= 1) m = fmaxf(m, __shfl_xor_sync(0xffffffffu, m, o));
        float sum = 0.f;
        for (int j = lane; j < KWIN; j += 32) {
            float e = __expf(row[j] - m);
            row[j] = e; sum += e;
        }
        #pragma unroll
        for (int o = 16; o; o >>= 1) sum += __shfl_xor_sync(0xffffffffu, sum, o);
        float inv = 1.f / sum;
        for (int j = lane; j < KWIN; j += 32) row[j] *= inv;
    }
    __syncthreads();

    // output: one thread per (qi, d-group-of-4): 61*4 = 244 items
    if (t < WIN*4) {
        int qi = t >> 2, d4 = t & 3;
        const float* row = sc + qi*(KWIN+1);
        float4 acc = make_float4(0.f, 0.f, 0.f, 0.f);
        for (int j = 0; j < KWIN; j++) {
            float p = row[j];
            float4 vv = *(const float4*)(vs + j*DHD + d4*4);
            acc.x += p*vv.x; acc.y += p*vv.y; acc.z += p*vv.z; acc.w += p*vv.w;
        }
        int s = nw*WIN + qi;
        *(float4*)(ao + ((size_t)b*SS + s)*DD + h*DHD + d4*4) = acc;
    }
}

// ---------------- final head: out = A @ pre_w2 + b ----------------
__global__ void head2_kernel(const float* __restrict__ A, const float* __restrict__ w2,
                             const float* __restrict__ b2, float* __restrict__ out) {
    int warp = threadIdx.x >> 5, lane = threadIdx.x & 31;
    long long row = (long long)blockIdx.x * 8 + warp;
    if (row >= BS) return;
    float4 a = ((const float4*)(A + row*DD))[lane];
    float4 w = ((const float4*)w2)[lane];
    float s = a.x*w.x + a.y*w.y + a.z*w.z + a.w*w.w;
    #pragma unroll
    for (int o = 16; o; o >>= 1) s += __shfl_xor_sync(0xffffffffu, s, o);
    if (lane == 0) out[row] = s + b2[0];
}

// ---------------- launch ----------------
extern "C" void kernel_launch(void* const* d_in, const int* in_sizes, int n_in,
                              void* d_out, int out_size) {
    const float* x      = (const float*)d_in[0];
    const float* conv_w = (const float*)d_in[1];
    const float* conv_b = (const float*)d_in[2];
    const float* lt_w   = (const float*)d_in[3];
    const float* lt_b   = (const float*)d_in[4];
    const float* pos    = (const float*)d_in[5];
    const float* ln1_s  = (const float*)d_in[6];
    const float* ln1_b  = (const float*)d_in[7];
    const float* wq     = (const float*)d_in[8];
    const float* wk     = (const float*)d_in[9];
    const float* wv     = (const float*)d_in[10];
    const float* wo     = (const float*)d_in[11];
    const float* wo_b   = (const float*)d_in[12];
    const float* ln2_s  = (const float*)d_in[13];
    const float* ln2_b  = (const float*)d_in[14];
    const float* ff_w1  = (const float*)d_in[15];
    const float* ff_b1  = (const float*)d_in[16];
    const float* ff_w2  = (const float*)d_in[17];
    const float* ff_b2  = (const float*)d_in[18];
    const float* pre_w1 = (const float*)d_in[19];
    const float* pre_b1 = (const float*)d_in[20];
    const float* pre_w2 = (const float*)d_in[21];
    const float* pre_b2 = (const float*)d_in[22];
    float* out = (float*)d_out;

    float *h, *t, *q, *k, *v, *ao, *ff;
    cudaGetSymbolAddress((void**)&h,  g_h);
    cudaGetSymbolAddress((void**)&t,  g_t);
    cudaGetSymbolAddress((void**)&q,  g_q);
    cudaGetSymbolAddress((void**)&k,  g_k);
    cudaGetSymbolAddress((void**)&v,  g_v);
    cudaGetSymbolAddress((void**)&ao, g_ao);
    cudaGetSymbolAddress((void**)&ff, g_ff);

    cudaFuncSetAttribute(attn_kernel, cudaFuncAttributeMaxDynamicSharedMemorySize, ATTN_SMEM);

    embed_kernel<<<BS, 128>>>(x, conv_w, conv_b, lt_w, lt_b, pos, h);

    dim3 gD(DD  / GBN, (BS + GBM - 1) / GBM);   // (2, 931)
    dim3 gF(FFD / GBN, (BS + GBM - 1) / GBM);   // (8, 931)
    int lnGrid = (BS + 7) / 8;

    for (int l = 0; l < LL; l++) {
        ln_kernel<<<lnGrid, 256>>>(h, ln1_s + l*DD, ln1_b + l*DD, t);
        gemm_kernel<<<gD, 256>>>(t, wq + (size_t)l*DD*DD, nullptr, nullptr, q, BS, DD, DD, 0.25f, 0);
        gemm_kernel<<<gD, 256>>>(t, wk + (size_t)l*DD*DD, nullptr, nullptr, k, BS, DD, DD, 1.f,   0);
        gemm_kernel<<<gD, 256>>>(t, wv + (size_t)l*DD*DD, nullptr, nullptr, v, BS, DD, DD, 1.f,   0);
        attn_kernel<<<dim3(NWIN, HH, BB), 256, ATTN_SMEM>>>(q, k, v, ao);
        gemm_kernel<<<gD, 256>>>(ao, wo + (size_t)l*DD*DD, wo_b + l*DD, h, h, BS, DD, DD, 1.f, 0);
        ln_kernel<<<lnGrid, 256>>>(h, ln2_s + l*DD, ln2_b + l*DD, t);
        gemm_kernel<<<gF, 256>>>(t, ff_w1 + (size_t)l*DD*FFD, ff_b1 + l*FFD, nullptr, ff, BS, FFD, DD, 1.f, 2);
        gemm_kernel<<<gD, 256>>>(ff, ff_w2 + (size_t)l*FFD*DD, ff_b2 + l*DD, h, h, BS, DD, FFD, 1.f, 0);
    }

    gemm_kernel<<<gD, 256>>>(h, pre_w1, pre_b1, nullptr, t, BS, DD, DD, 1.f, 1);
    head2_kernel<<<lnGrid, 256>>>(t, pre_w2, pre_b2, out);
}